// round 4
// baseline (speedup 1.0000x reference)
#include <cuda_runtime.h>

// DTW 65536 x 512 — 16 single-warp CTAs, 1 column/lane, R=16 rows/tick.
// ac[r][j] = min(ac[r-1][j-1], ac[r-1][j], ac[r][j-1]) + (k[j]-x[r])^2
// Column j: CTA j/32, lane j%32. Lane skew 1 tick; intra-warp handoff via
// shfl_up (branchless SEL against a broadcast LDS for lane 0). Cross-CTA
// handoff via __device__ edge arrays + release/acquire flags, staged into
// double-buffered smem in 32-tick chunks. No __syncthreads anywhere.

#define N_ROWS  65536
#define KLEN    512
#define NCTA    16
#define R       16
#define NTICK   (N_ROWS / R)           // 4096
#define NITER   (NTICK + 31)           // 4127
#define RING    4096
#define RINGM   (RING - 1)
#define CHUNK   32                     // ticks per cross-CTA chunk

__device__ __align__(16) float g_edge[NCTA - 1][N_ROWS];
__device__ int g_flag[NCTA - 1];

__global__ void dtw_init_flags()
{
    if (threadIdx.x < NCTA - 1) g_flag[threadIdx.x] = 0;
}

__device__ __forceinline__ int flag_acquire(const int* p)
{
    int v;
    asm volatile("ld.acquire.gpu.global.b32 %0, [%1];" : "=r"(v) : "l"(p) : "memory");
    return v;
}

__device__ __forceinline__ void flag_release(int* p, int v)
{
    asm volatile("st.release.gpu.global.b32 [%0], %1;" :: "l"(p), "r"(v) : "memory");
}

__global__ __launch_bounds__(32, 1)
void dtw_warp_kernel(const float* __restrict__ x,
                     const float* __restrict__ kern,
                     float* __restrict__ out)
{
    __shared__ __align__(16) float ring[RING];              // 16 KB x window
    __shared__ __align__(16) float lbuf[2][CHUNK * R];      // 4 KB edge staging

    const int   c   = (int)blockIdx.x;
    const int   l   = (int)threadIdx.x;
    const float INF = __int_as_float(0x7f800000);

    const float kv = kern[c * 32 + l];

    // preload x rows [0, 4096): 1024 float4, 32 per lane
    #pragma unroll
    for (int k = 0; k < 32; ++k)
        ((float4*)ring)[l + 32 * k] = ((const float4*)x)[l + 32 * k];

    if (c == 0) {
        // lane 0 of CTA 0 must see +INF left boundary; fill both buffers.
        float* lf = &lbuf[0][0];
        #pragma unroll
        for (int k = 0; k < (2 * CHUNK * R) / 32; ++k)
            lf[l + 32 * k] = INF;
    } else {
        // stage chunk 0: ticks [0, 32)
        if (l == 0) {
            while (flag_acquire(&g_flag[c - 1]) < CHUNK) { }
        }
        __syncwarp();
        #pragma unroll
        for (int k = 0; k < 4; ++k) {
            float4 v = __ldcg((const float4*)(g_edge[c - 1] + l * R + 4 * k));
            *(float4*)&lbuf[0][l * R + 4 * k] = v;
        }
    }
    __syncwarp();

    float ev[R];
    #pragma unroll
    for (int r = 0; r < R; ++r) ev[r] = 0.0f;
    float vprev = INF, dlast = INF;

    for (int i = 0; i < NITER; ++i) {
        // ---- previous tick's outputs from left lane ----
        float Lsh[R];
        #pragma unroll
        for (int r = 0; r < R; ++r)
            Lsh[r] = __shfl_up_sync(0xffffffffu, ev[r], 1);

        // ---- chunk maintenance every 32 ticks ----
        if ((i & (CHUNK - 1)) == 0) {
            // x refill: rows [16i+2048, +512); region is 512-aligned.
            const int rbase = 16 * i + 2048;
            if (rbase < N_ROWS) {
                #pragma unroll
                for (int k = 0; k < 4; ++k) {
                    float4 v = *(const float4*)(x + rbase + l * 16 + 4 * k);
                    *(float4*)&ring[((unsigned)rbase & RINGM) + l * 16 + 4 * k] = v;
                }
            }
            // edge staging: ticks [i+32, i+64)
            if (c > 0) {
                const int base = i + CHUNK;
                if (base < NTICK) {
                    if (l == 0) {
                        const int need = base + CHUNK;
                        while (flag_acquire(&g_flag[c - 1]) < need) { }
                    }
                    __syncwarp();
                    const int buf = ((i >> 5) + 1) & 1;
                    #pragma unroll
                    for (int k = 0; k < 4; ++k) {
                        float4 v = __ldcg((const float4*)(g_edge[c - 1] + base * R + l * R + 4 * k));
                        *(float4*)&lbuf[buf][l * R + 4 * k] = v;
                    }
                }
            }
            __syncwarp();
        }

        // ---- left boundary values: branchless (broadcast LDS + SEL) ----
        const float* lb = &lbuf[(i >> 5) & 1][(i & (CHUNK - 1)) * R];
        const float4 b0 = *(const float4*)(lb + 0);
        const float4 b1 = *(const float4*)(lb + 4);
        const float4 b2 = *(const float4*)(lb + 8);
        const float4 b3 = *(const float4*)(lb + 12);
        const float Lld[R] = {b0.x, b0.y, b0.z, b0.w, b1.x, b1.y, b1.z, b1.w,
                              b2.x, b2.y, b2.z, b2.w, b3.x, b3.y, b3.z, b3.w};
        float L[R];
        #pragma unroll
        for (int r = 0; r < R; ++r)
            L[r] = (l == 0) ? Lld[r] : Lsh[r];
        // virtual 0 at (row 0, col -1): left-use only, at cell (0,0)
        if (i == 0 && c == 0 && l == 0) L[0] = 0.0f;

        const int  t      = i - l;
        const bool active = (t >= 0) && (t < NTICK);

        // ---- x values for my 16 rows (slot multiple of 16 -> float4 ok) ----
        const unsigned xo = ((unsigned)(t * R)) & RINGM;
        const float4 xa = *(const float4*)&ring[xo];
        const float4 xb = *(const float4*)&ring[xo + 4];
        const float4 xc = *(const float4*)&ring[xo + 8];
        const float4 xd = *(const float4*)&ring[xo + 12];
        const float xs[R] = {xa.x, xa.y, xa.z, xa.w, xb.x, xb.y, xb.z, xb.w,
                             xc.x, xc.y, xc.z, xc.w, xd.x, xd.y, xd.z, xd.w};

        // ---- off-chain: m[r] = min(diag, left) ----
        float m[R];
        m[0] = fminf(dlast, L[0]);
        #pragma unroll
        for (int r = 1; r < R; ++r) m[r] = fminf(L[r - 1], L[r]);

        // ---- serial chain: v = min(m, vprev) + d ----
        float v[R];
        float vp = vprev;
        #pragma unroll
        for (int r = 0; r < R; ++r) {
            const float tt = kv - xs[r];
            const float d  = tt * tt;
            vp = fminf(m[r], vp) + d;
            v[r] = vp;
        }

        if (active) {
            #pragma unroll
            for (int r = 0; r < R; ++r) ev[r] = v[r];
            vprev = vp;
            dlast = L[R - 1];

            if (l == 31) {
                if (c < NCTA - 1) {
                    float* ep = g_edge[c] + t * R;
                    *(float4*)(ep + 0)  = make_float4(v[0],  v[1],  v[2],  v[3]);
                    *(float4*)(ep + 4)  = make_float4(v[4],  v[5],  v[6],  v[7]);
                    *(float4*)(ep + 8)  = make_float4(v[8],  v[9],  v[10], v[11]);
                    *(float4*)(ep + 12) = make_float4(v[12], v[13], v[14], v[15]);
                    if ((t & 15) == 15)
                        flag_release(&g_flag[c], t + 1);
                } else {
                    float* op = out + t * R;
                    *(float4*)(op + 0)  = make_float4(v[0],  v[1],  v[2],  v[3]);
                    *(float4*)(op + 4)  = make_float4(v[4],  v[5],  v[6],  v[7]);
                    *(float4*)(op + 8)  = make_float4(v[8],  v[9],  v[10], v[11]);
                    *(float4*)(op + 12) = make_float4(v[12], v[13], v[14], v[15]);
                }
            }
        }
    }
}

extern "C" void kernel_launch(void* const* d_in, const int* in_sizes, int n_in,
                              void* d_out, int out_size)
{
    const float* x = (const float*)d_in[0];   // input  [65536]
    const float* k = (const float*)d_in[1];   // kernel [512]
    float* out = (float*)d_out;               // [65536] float32

    dtw_init_flags<<<1, 32>>>();
    dtw_warp_kernel<<<NCTA, 32>>>(x, k, out);
}

// round 5
// speedup vs baseline: 6.1371x; 6.1371x over previous
#include <cuda_runtime.h>

// DTW 65536 x 512 — 4 CTAs x 128 threads, 1 column/lane, R=16 rows/tick.
// ac[r][j] = min(ac[r-1][j-1], ac[r-1][j], ac[r][j-1]) + (k[j]-x[r])^2
// Column j: CTA j/128, thread j%128. Thread skew 1 tick/column.
//   intra-warp  handoff: shfl_up + SEL (branchless)
//   intra-CTA   handoff: double-buffered smem edge slots + per-tick barrier
//   cross-CTA   handoff: global edge arrays + release/acquire flags,
//                        staged into double-buffered smem in 32-tick chunks
// x is read straight from global with a one-iteration register prefetch.

#define N_ROWS  65536
#define NCTA    4
#define NTHR    128
#define NWARP   4
#define R       16
#define NTICK   (N_ROWS / R)          // 4096
#define NITER   (NTICK + NTHR - 1)    // 4223
#define CHUNK   32                    // ticks per cross-CTA chunk

__device__ __align__(16) float g_edge[NCTA - 1][N_ROWS];
__device__ int g_flag[NCTA - 1];

__global__ void dtw_init_flags()
{
    if (threadIdx.x < NCTA - 1) g_flag[threadIdx.x] = 0;
}

__device__ __forceinline__ int flag_acquire(const int* p)
{
    int v;
    asm volatile("ld.acquire.gpu.global.b32 %0, [%1];" : "=r"(v) : "l"(p) : "memory");
    return v;
}

__device__ __forceinline__ void flag_release(int* p, int v)
{
    asm volatile("st.release.gpu.global.b32 [%0], %1;" :: "l"(p), "r"(v) : "memory");
}

__global__ __launch_bounds__(NTHR, 1)
void dtw_pipe16_kernel(const float* __restrict__ x,
                       const float* __restrict__ kern,
                       float* __restrict__ out)
{
    __shared__ __align__(16) float  lbuf[2][CHUNK * R];   // 4 KB cross-CTA staging
    __shared__ __align__(16) float4 edgebuf[2][NWARP][4]; // intra-CTA handoff

    const int   c   = (int)blockIdx.x;
    const int   tid = (int)threadIdx.x;
    const int   w   = tid >> 5;
    const int   l   = tid & 31;
    const float INF = __int_as_float(0x7f800000);

    const float kv    = kern[c * NTHR + tid];
    const bool  pred0 = (c == 0) && (tid == 0);

    // ---- prestage chunk 0 of the left-CTA boundary ----
    if (c == 0) {
        // CTA 0's left boundary is +INF everywhere (both buffers, never restaged)
        #pragma unroll
        for (int k = 0; k < (2 * CHUNK * R) / NTHR; ++k)
            lbuf[0][tid + NTHR * k] = INF;
    } else {
        if (tid == 0) {
            while (flag_acquire(&g_flag[c - 1]) < CHUNK) { }
        }
        __syncthreads();
        *(float4*)&lbuf[0][4 * tid] = __ldcg((const float4*)g_edge[c - 1] + tid);
    }
    __syncthreads();

    float ev[R];
    #pragma unroll
    for (int r = 0; r < R; ++r) ev[r] = INF;
    float vprev = INF, dlast = INF;

    // x prefetch registers for iteration 0 (t = -tid, clamped to 0)
    const float4* x4 = (const float4*)x;
    float4 xn0 = x4[0], xn1 = x4[1], xn2 = x4[2], xn3 = x4[3];

    for (int i = 0; i < NITER; ++i) {
        // ---- left-neighbor values (previous tick's ev of lane l-1) ----
        float L[R];
        #pragma unroll
        for (int r = 0; r < R; ++r)
            L[r] = __shfl_up_sync(0xffffffffu, ev[r], 1);

        // ---- consume current x, prefetch next iteration's x ----
        const float xs[R] = {xn0.x, xn0.y, xn0.z, xn0.w, xn1.x, xn1.y, xn1.z, xn1.w,
                             xn2.x, xn2.y, xn2.z, xn2.w, xn3.x, xn3.y, xn3.z, xn3.w};
        {
            int tn = i + 1 - tid;
            tn = tn < 0 ? 0 : (tn >= NTICK ? NTICK - 1 : tn);
            const float4* xp = (const float4*)(x + tn * R);
            xn0 = xp[0]; xn1 = xp[1]; xn2 = xp[2]; xn3 = xp[3];
        }

        // ---- cross-CTA chunk staging every 32 ticks ----
        if ((i & (CHUNK - 1)) == 0) {
            if (c > 0) {
                const int base = i + CHUNK;
                if (base < NTICK) {
                    if (tid == 0) {
                        const int need = base + CHUNK;
                        while (flag_acquire(&g_flag[c - 1]) < need) { }
                    }
                    __syncthreads();
                    const int buf = ((i >> 5) + 1) & 1;
                    *(float4*)&lbuf[buf][4 * tid] =
                        __ldcg((const float4*)(g_edge[c - 1] + base * R) + tid);
                    // consumed >= 32 iterations later; the per-iteration
                    // barrier below orders these STS before those reads.
                }
            }
        }

        // ---- lane-0 boundary source (warp-uniform branch, broadcast LDS) ----
        float4 e0, e1, e2, e3;
        if (w == 0) {
            const float4* lb = (const float4*)&lbuf[(i >> 5) & 1][(i & (CHUNK - 1)) * R];
            e0 = lb[0]; e1 = lb[1]; e2 = lb[2]; e3 = lb[3];
        } else {
            const float4* eb = (const float4*)edgebuf[(i & 1) ^ 1][w - 1];
            e0 = eb[0]; e1 = eb[1]; e2 = eb[2]; e3 = eb[3];
        }
        {
            const float Lb[R] = {e0.x, e0.y, e0.z, e0.w, e1.x, e1.y, e1.z, e1.w,
                                 e2.x, e2.y, e2.z, e2.w, e3.x, e3.y, e3.z, e3.w};
            #pragma unroll
            for (int r = 0; r < R; ++r)
                L[r] = (l == 0) ? Lb[r] : L[r];
        }
        // virtual 0 at (row 0, col -1): left-use only, at cell (0,0)
        L[0] = (pred0 && i == 0) ? 0.0f : L[0];

        const int  t      = i - tid;
        const bool active = (t >= 0) && (t < NTICK);

        // ---- m = min(diag, left), in place (descending keeps deps correct) ----
        const float lastL = L[R - 1];
        #pragma unroll
        for (int r = R - 1; r >= 1; --r)
            L[r] = fminf(L[r - 1], L[r]);
        L[0] = fminf(dlast, L[0]);

        // ---- off-chain residuals, then the 8-cyc/row serial chain ----
        float ts[R];
        #pragma unroll
        for (int r = 0; r < R; ++r) ts[r] = kv - xs[r];

        float vp = vprev;
        #pragma unroll
        for (int r = 0; r < R; ++r) {
            vp = fmaf(ts[r], ts[r], fminf(L[r], vp));
            ev[r] = vp;     // unconditional commit: inactive lanes' ev is
                            // only ever consumed by inactive neighbors
        }
        vprev = active ? vp : vprev;
        dlast = active ? lastL : dlast;

        // ---- publish right edge ----
        if (l == 31 && active) {
            const float4 a = make_float4(ev[0],  ev[1],  ev[2],  ev[3]);
            const float4 b = make_float4(ev[4],  ev[5],  ev[6],  ev[7]);
            const float4 d = make_float4(ev[8],  ev[9],  ev[10], ev[11]);
            const float4 e = make_float4(ev[12], ev[13], ev[14], ev[15]);
            if (w < NWARP - 1) {
                float4* eb = edgebuf[i & 1][w];
                eb[0] = a; eb[1] = b; eb[2] = d; eb[3] = e;
            } else if (c < NCTA - 1) {
                float4* ep = (float4*)(g_edge[c] + t * R);
                ep[0] = a; ep[1] = b; ep[2] = d; ep[3] = e;
                if ((t & 15) == 15)
                    flag_release(&g_flag[c], t + 1);
            } else {
                float4* op = (float4*)(out + t * R);
                op[0] = a; op[1] = b; op[2] = d; op[3] = e;
            }
        }

        __syncthreads();
    }
}

extern "C" void kernel_launch(void* const* d_in, const int* in_sizes, int n_in,
                              void* d_out, int out_size)
{
    const float* x = (const float*)d_in[0];   // input  [65536]
    const float* k = (const float*)d_in[1];   // kernel [512]
    float* out = (float*)d_out;               // [65536] float32

    dtw_init_flags<<<1, 32>>>();
    dtw_pipe16_kernel<<<NCTA, NTHR>>>(x, k, out);
}